// round 6
// baseline (speedup 1.0000x reference)
#include <cuda_runtime.h>
#include <math.h>
#include <stdint.h>

// Problem constants
#define BB 2
#define LL 4096
#define DD 512
#define HH 8
#define EE 64
#define CC 64
#define NC (LL/CC)         // 64
#define MM (BB*LL)         // 8192

// ---------------- scratch (device globals; no allocation) ----------------
__device__ float g_q[MM*DD];
__device__ float g_k[MM*DD];
__device__ float g_v[MM*DD];
__device__ float g_loglam[MM*HH];
__device__ float g_cum[MM*HH];
__device__ float g_state[(size_t)BB*HH*NC*EE*EE];   // S_T[f][e] per chunk -> exclusive prefix
__device__ float g_zstate[BB*HH*NC*EE];
__device__ float g_attn[MM*DD];                     // tf32-rounded, k-interleaved
__device__ float g_proj[MM*DD];                     // reused as rounded/interleaved x pre-gemm0
__device__ float g_wq[3*DD*DD];                     // rounded + k-interleaved qkv_w
__device__ float g_wo[DD*DD];                       // rounded + k-interleaved out_w
#define g_xr g_proj

// k-interleave within each 8-block: physical order [l0,l4,l1,l5,l2,l6,l3,l7]
// => logical (tig, tig+4) sit at physical (2*tig, 2*tig+1): one float2.

// ---------------- helpers ----------------
__device__ __forceinline__ uint32_t f2tf32(float f) {
    uint32_t u;
    asm("cvt.rna.tf32.f32 %0, %1;" : "=r"(u) : "f"(f));
    return u;
}
__device__ __forceinline__ float rtf(float f) { return __uint_as_float(f2tf32(f)); }

__device__ __forceinline__ void mma_tf32(float c[4], const uint32_t a[4],
                                         uint32_t b0, uint32_t b1) {
    asm volatile(
        "mma.sync.aligned.m16n8k8.row.col.f32.tf32.tf32.f32 "
        "{%0,%1,%2,%3}, {%4,%5,%6,%7}, {%8,%9}, {%0,%1,%2,%3};"
        : "+f"(c[0]), "+f"(c[1]), "+f"(c[2]), "+f"(c[3])
        : "r"(a[0]), "r"(a[1]), "r"(a[2]), "r"(a[3]), "r"(b0), "r"(b1));
}
__device__ __forceinline__ void cp_async16(uint32_t s, const void* g) {
    asm volatile("cp.async.ca.shared.global [%0], [%1], 16;" :: "r"(s), "l"(g));
}
__device__ __forceinline__ void cp_commit() { asm volatile("cp.async.commit_group;"); }
template<int N>
__device__ __forceinline__ void cp_wait() {
    asm volatile("cp.async.wait_group %0;" :: "n"(N));
}

// ---------------- tensor-core GEMM: C = A @ W^T + bias ----------------
// Operands pre-rounded to tf32 AND k-interleaved. PITCH 40 => conflict-free
// float2 fragment loads (row stride = 8 banks).
#define SPITCH 40
#define ASZ (128 * SPITCH)

template<int MODE>
__global__ __launch_bounds__(256, 2)
void gemm_tc(const float* __restrict__ bias)
{
    extern __shared__ float sm[];
    const float* A = (MODE == 0) ? g_xr : g_attn;
    const float* W = (MODE == 0) ? g_wq : g_wo;

    const int tid  = threadIdx.x;
    const int w    = tid >> 5;
    const int lane = tid & 31;
    const int g    = lane >> 2;
    const int tig  = lane & 3;
    const int warpM = (w & 3) * 32;
    const int warpN = (w >> 2) * 64;
    const int bm = blockIdx.y * 128;
    const int bn = blockIdx.x * 128;

    float acc[2][8][4];
#pragma unroll
    for (int mt = 0; mt < 2; mt++)
#pragma unroll
        for (int nt = 0; nt < 8; nt++)
#pragma unroll
            for (int i = 0; i < 4; i++) acc[mt][nt][i] = 0.f;

    const int lrow0 = tid >> 3;
    const int lcol  = (tid & 7) * 4;

    uint32_t sbase = (uint32_t)__cvta_generic_to_shared((void*)sm);
    auto stage_issue = [&](int kc, int st) {
        uint32_t as = sbase + (uint32_t)(st * 2 * ASZ) * 4u;
        uint32_t ws = as + (uint32_t)ASZ * 4u;
#pragma unroll
        for (int i = 0; i < 4; i++) {
            int row = lrow0 + i * 32;
            cp_async16(as + (uint32_t)(row * SPITCH + lcol) * 4u,
                       A + (size_t)(bm + row) * DD + kc * 32 + lcol);
            cp_async16(ws + (uint32_t)(row * SPITCH + lcol) * 4u,
                       W + (size_t)(bn + row) * DD + kc * 32 + lcol);
        }
        cp_commit();
    };

    stage_issue(0, 0);

    const int NKC = DD / 32;
    for (int kc = 0; kc < NKC; kc++) {
        if (kc + 1 < NKC) { stage_issue(kc + 1, (kc + 1) & 1); cp_wait<1>(); }
        else               { cp_wait<0>(); }
        __syncthreads();

        const float* As = sm + (kc & 1) * 2 * ASZ;
        const float* Ws = As + ASZ;

#pragma unroll
        for (int kk = 0; kk < 4; kk++) {
            const int k0 = kk * 8 + 2 * tig;
            uint32_t a[2][4];
#pragma unroll
            for (int mt = 0; mt < 2; mt++) {
                const int r0 = warpM + mt * 16 + g;
                float2 p0 = *(const float2*)&As[(r0    ) * SPITCH + k0];
                float2 p1 = *(const float2*)&As[(r0 + 8) * SPITCH + k0];
                a[mt][0] = __float_as_uint(p0.x);
                a[mt][1] = __float_as_uint(p1.x);
                a[mt][2] = __float_as_uint(p0.y);
                a[mt][3] = __float_as_uint(p1.y);
            }
#pragma unroll
            for (int nt = 0; nt < 8; nt++) {
                float2 bp = *(const float2*)&Ws[(warpN + nt * 8 + g) * SPITCH + k0];
                uint32_t b0 = __float_as_uint(bp.x);
                uint32_t b1 = __float_as_uint(bp.y);
                mma_tf32(acc[0][nt], a[0], b0, b1);
                mma_tf32(acc[1][nt], a[1], b0, b1);
            }
        }
        __syncthreads();
    }

    const int nbase = bn + warpN;
    if (MODE == 0) {
        const int sec = nbase >> 9;
        const int colbase = nbase & 511;
        const int h = colbase >> 6;
        float* dst = (sec == 0) ? g_q : (sec == 1) ? g_k : g_v;
        float fac[2][2];
#pragma unroll
        for (int mt = 0; mt < 2; mt++)
#pragma unroll
            for (int rh = 0; rh < 2; rh++) {
                const int m = bm + warpM + mt * 16 + g + rh * 8;
                const float c = g_cum[m * HH + h];
                fac[mt][rh] = (sec == 0) ? __expf(c) * 0.125f
                            : (sec == 1) ? __expf(-c) : 1.f;
            }
#pragma unroll
        for (int mt = 0; mt < 2; mt++)
#pragma unroll
            for (int nt = 0; nt < 8; nt++) {
                const int ng = nbase + nt * 8 + tig * 2;
                const float b0 = bias[ng], b1 = bias[ng + 1];
                const int coln = colbase + nt * 8 + tig * 2;
#pragma unroll
                for (int rh = 0; rh < 2; rh++) {
                    const int m = bm + warpM + mt * 16 + g + rh * 8;
                    float v0 = acc[mt][nt][2 * rh    ] + b0;
                    float v1 = acc[mt][nt][2 * rh + 1] + b1;
                    if (sec < 2) {
                        v0 = (v0 > 0.f) ? (v0 + 1.f) : __expf(v0);
                        v1 = (v1 > 0.f) ? (v1 + 1.f) : __expf(v1);
                        v0 *= fac[mt][rh];
                        v1 *= fac[mt][rh];
                    }
                    float2 o; o.x = v0; o.y = v1;
                    *(float2*)(dst + (size_t)m * DD + coln) = o;
                }
            }
    } else {
#pragma unroll
        for (int mt = 0; mt < 2; mt++)
#pragma unroll
            for (int nt = 0; nt < 8; nt++) {
                const int ng = nbase + nt * 8 + tig * 2;
                const float b0 = bias[ng], b1 = bias[ng + 1];
#pragma unroll
                for (int rh = 0; rh < 2; rh++) {
                    const int m = bm + warpM + mt * 16 + g + rh * 8;
                    float2 o;
                    o.x = acc[mt][nt][2 * rh    ] + b0;
                    o.y = acc[mt][nt][2 * rh + 1] + b1;
                    *(float2*)(g_proj + (size_t)m * DD + ng) = o;
                }
            }
    }
}

// ---------------- round + k-interleave all GEMM operands ----------------
// unit = one 8-float logical block. out phys = [l0,l4,l1,l5,l2,l6,l3,l7]
__global__ __launch_bounds__(256)
void roundw_kernel(const float* __restrict__ qkv_w, const float* __restrict__ out_w,
                   const float* __restrict__ x)
{
    const int u = blockIdx.x * 256 + threadIdx.x;
    const int NQ = 3 * DD * DD / 8;
    const int NO = DD * DD / 8;
    const float4* src;
    float4* dst;
    int idx;
    if (u < NQ)           { src = (const float4*)qkv_w; dst = (float4*)g_wq; idx = u; }
    else if (u < NQ + NO) { src = (const float4*)out_w; dst = (float4*)g_wo; idx = u - NQ; }
    else                  { src = (const float4*)x;     dst = (float4*)g_xr; idx = u - NQ - NO; }
    float4 i0 = src[2 * idx], i1 = src[2 * idx + 1];
    float4 o0, o1;
    o0.x = rtf(i0.x); o0.y = rtf(i1.x); o0.z = rtf(i0.y); o0.w = rtf(i1.y);
    o1.x = rtf(i0.z); o1.y = rtf(i1.z); o1.z = rtf(i0.w); o1.w = rtf(i1.w);
    dst[2 * idx] = o0;
    dst[2 * idx + 1] = o1;
}

// ---------------- decay logits ----------------
__global__ __launch_bounds__(256)
void decay_kernel(const float* __restrict__ x, const float* __restrict__ dw,
                  const float* __restrict__ db)
{
    const int m = blockIdx.x;
    const int h = threadIdx.x >> 5;
    const int lane = threadIdx.x & 31;
    const float* xr = x + (size_t)m * DD;
    const float* wr = dw + h * DD;
    float s = 0.f;
    for (int k = lane * 4; k < DD; k += 128) {
        float4 xv = *(const float4*)(xr + k);
        float4 wv = *(const float4*)(wr + k);
        s += xv.x * wv.x + xv.y * wv.y + xv.z * wv.z + xv.w * wv.w;
    }
#pragma unroll
    for (int off = 16; off; off >>= 1) s += __shfl_xor_sync(0xffffffffu, s, off);
    if (lane == 0) {
        float logit = s + db[h];
        float lam = 0.9f + 0.1f / (1.f + expf(-logit));
        g_loglam[m * HH + h] = logf(lam);
    }
}

// ---------------- cumsum of log-lambda along L ----------------
__global__ __launch_bounds__(256)
void cumsum_kernel()
{
    const int b = blockIdx.x >> 3;
    const int h = blockIdx.x & 7;
    const int tid = threadIdx.x;
    float vals[16];
    float s = 0.f;
    const int base = (b * LL + tid * 16) * HH + h;
#pragma unroll
    for (int i = 0; i < 16; i++) { s += g_loglam[base + i * HH]; vals[i] = s; }
    __shared__ float ts[256];
    ts[tid] = s;
    __syncthreads();
    for (int off = 1; off < 256; off <<= 1) {
        float v = (tid >= off) ? ts[tid - off] : 0.f;
        __syncthreads();
        ts[tid] += v;
        __syncthreads();
    }
    const float prev = (tid > 0) ? ts[tid - 1] : 0.f;
#pragma unroll
    for (int i = 0; i < 16; i++) {
        float c = prev + vals[i];
        c = fminf(50.f, fmaxf(-50.f, c));
        g_cum[base + i * HH] = c;
    }
}

// ---------------- per-chunk transposed KV state + k-sum ----------------
#define TP 65
__global__ __launch_bounds__(128)
void chunkstate_mma()
{
    __shared__ float kT[64 * TP];
    __shared__ float vT[64 * TP];
    const int c = blockIdx.x & (NC - 1);
    const int h = (blockIdx.x >> 6) & 7;
    const int b = blockIdx.x >> 9;
    const int bh = b * HH + h;
    const int tid = threadIdx.x;
    const int w = tid >> 5;
    const int lane = tid & 31;
    const int g = lane >> 2;
    const int tig = lane & 3;
    const int rowbase = b * LL + c * CC;

#pragma unroll
    for (int it = 0; it < 8; it++) {
        int idx4 = tid + it * 128;
        int t = idx4 >> 4;
        int e4 = (idx4 & 15) << 2;
        size_t gidx = (size_t)(rowbase + t) * DD + h * EE + e4;
        float4 kv = *(const float4*)(g_k + gidx);
        float4 vv = *(const float4*)(g_v + gidx);
        kT[(e4 + 0) * TP + t] = kv.x; kT[(e4 + 1) * TP + t] = kv.y;
        kT[(e4 + 2) * TP + t] = kv.z; kT[(e4 + 3) * TP + t] = kv.w;
        vT[(e4 + 0) * TP + t] = vv.x; vT[(e4 + 1) * TP + t] = vv.y;
        vT[(e4 + 2) * TP + t] = vv.z; vT[(e4 + 3) * TP + t] = vv.w;
    }
    __syncthreads();

    const int f0 = w * 16;
    float acc[8][4];
#pragma unroll
    for (int nt = 0; nt < 8; nt++)
#pragma unroll
        for (int i = 0; i < 4; i++) acc[nt][i] = 0.f;

#pragma unroll
    for (int kk = 0; kk < 8; kk++) {
        const int k0 = kk * 8;
        uint32_t a[4];
        a[0] = f2tf32(vT[(f0 + g    ) * TP + k0 + tig    ]);
        a[1] = f2tf32(vT[(f0 + g + 8) * TP + k0 + tig    ]);
        a[2] = f2tf32(vT[(f0 + g    ) * TP + k0 + tig + 4]);
        a[3] = f2tf32(vT[(f0 + g + 8) * TP + k0 + tig + 4]);
#pragma unroll
        for (int nt = 0; nt < 8; nt++) {
            uint32_t b0 = f2tf32(kT[(nt * 8 + g) * TP + k0 + tig    ]);
            uint32_t b1 = f2tf32(kT[(nt * 8 + g) * TP + k0 + tig + 4]);
            mma_tf32(acc[nt], a, b0, b1);
        }
    }

    const size_t sb = ((size_t)bh * NC + c) * (EE * EE);
#pragma unroll
    for (int nt = 0; nt < 8; nt++) {
        const int e0 = nt * 8 + tig * 2;
        float2 s0; s0.x = acc[nt][0]; s0.y = acc[nt][1];
        float2 s1; s1.x = acc[nt][2]; s1.y = acc[nt][3];
        *(float2*)(g_state + sb + (f0 + g    ) * EE + e0) = s0;
        *(float2*)(g_state + sb + (f0 + g + 8) * EE + e0) = s1;
    }
    if (tid < 64) {
        float z = 0.f;
#pragma unroll 8
        for (int t = 0; t < CC; t++) z += kT[tid * TP + t];
        g_zstate[(bh * NC + c) * EE + tid] = z;
    }
}

// ---------------- exclusive scan over chunks ----------------
__global__ __launch_bounds__(256)
void statescan_kernel()
{
    const int bh = blockIdx.x >> 4;
    const int split = blockIdx.x & 15;
    const int elem = split * 256 + threadIdx.x;
    size_t base = (size_t)bh * NC * EE * EE + elem;
    float run = 0.f;
#pragma unroll 4
    for (int c = 0; c < NC; c++) {
        float v = g_state[base + (size_t)c * EE * EE];
        g_state[base + (size_t)c * EE * EE] = run;
        run += v;
    }
    if (split == 0 && threadIdx.x < 64) {
        size_t zb = (size_t)bh * NC * EE + threadIdx.x;
        float r = 0.f;
        for (int c = 0; c < NC; c++) {
            float v = g_zstate[zb + (size_t)c * EE];
            g_zstate[zb + (size_t)c * EE] = r;
            r += v;
        }
    }
}

// ---------------- intra-chunk attention (tensor cores) ----------------
#define IP 68
#define OQ 0
#define OK (64*IP)
#define OP (2*64*IP)
#define OS (3*64*IP)
#define OV (4*64*IP)
#define OZ (OV + 64*TP)
#define ODEN (OZ + 64)
#define ISMF (ODEN + 64)

__global__ __launch_bounds__(256)
void intra_mma()
{
    extern __shared__ float sm[];
    const int c = blockIdx.x & (NC - 1);
    const int h = (blockIdx.x >> 6) & 7;
    const int b = blockIdx.x >> 9;
    const int bh = b * HH + h;
    const int tid = threadIdx.x;
    const int w = tid >> 5;
    const int lane = tid & 31;
    const int g = lane >> 2;
    const int tig = lane & 3;
    const int rowbase = b * LL + c * CC;
    const size_t sb = ((size_t)bh * NC + c) * (EE * EE);

#pragma unroll
    for (int it = 0; it < 4; it++) {
        int idx4 = tid + it * 256;
        int t = idx4 >> 4;
        int e4 = (idx4 & 15) << 2;
        size_t gidx = (size_t)(rowbase + t) * DD + h * EE + e4;
        *(float4*)&sm[OQ + t * IP + e4] = *(const float4*)(g_q + gidx);
        *(float4*)&sm[OK + t * IP + e4] = *(const float4*)(g_k + gidx);
        float4 vv = *(const float4*)(g_v + gidx);
        sm[OV + (e4 + 0) * TP + t] = vv.x; sm[OV + (e4 + 1) * TP + t] = vv.y;
        sm[OV + (e4 + 2) * TP + t] = vv.z; sm[OV + (e4 + 3) * TP + t] = vv.w;
        *(float4*)&sm[OS + t * IP + e4] = *(const float4*)(g_state + sb + idx4 * 4);
    }
    if (tid < 64) sm[OZ + tid] = g_zstate[(bh * NC + c) * EE + tid];
    __syncthreads();

    const int wm = (w & 3) * 16;
    const int wn = (w >> 2) * 32;

    // phase 1: P[t][s] = sum_e q[t][e] k[s][e], masked s <= t
    {
        float pacc[4][4];
#pragma unroll
        for (int nt = 0; nt < 4; nt++)
#pragma unroll
            for (int i = 0; i < 4; i++) pacc[nt][i] = 0.f;
#pragma unroll
        for (int kk = 0; kk < 8; kk++) {
            const int k0 = kk * 8;
            uint32_t a[4];
            a[0] = f2tf32(sm[OQ + (wm + g    ) * IP + k0 + tig    ]);
            a[1] = f2tf32(sm[OQ + (wm + g + 8) * IP + k0 + tig    ]);
            a[2] = f2tf32(sm[OQ + (wm + g    ) * IP + k0 + tig + 4]);
            a[3] = f2tf32(sm[OQ + (wm + g + 8) * IP + k0 + tig + 4]);
#pragma unroll
            for (int nt = 0; nt < 4; nt++) {
                uint32_t b0 = f2tf32(sm[OK + (wn + nt * 8 + g) * IP + k0 + tig    ]);
                uint32_t b1 = f2tf32(sm[OK + (wn + nt * 8 + g) * IP + k0 + tig + 4]);
                mma_tf32(pacc[nt], a, b0, b1);
            }
        }
#pragma unroll
        for (int nt = 0; nt < 4; nt++) {
            const int scol = wn + nt * 8 + tig * 2;
            const int r0 = wm + g, r1 = wm + g + 8;
            float2 p0, p1;
            p0.x = (scol     <= r0) ? pacc[nt][0] : 0.f;
            p0.y = (scol + 1 <= r0) ? pacc[nt][1] : 0.f;
            p1.x = (scol     <= r1) ? pacc[nt][2] : 0.f;
            p1.y = (scol + 1 <= r1) ? pacc[nt][3] : 0.f;
            *(float2*)&sm[OP + r0 * IP + scol] = p0;
            *(float2*)&sm[OP + r1 * IP + scol] = p1;
        }
    }
    __syncthreads();

    // phase 2: denominators
    if (tid < 64) {
        const int t = tid;
        float s = 0.f;
#pragma unroll 8
        for (int s2 = 0; s2 < CC; s2++) s += sm[OP + t * IP + s2];
#pragma unroll 8
        for (int e = 0; e < EE; e++) s += sm[OQ + t * IP + e] * sm[OZ + e];
        sm[ODEN + t] = 1.f / (s + 1e-6f);
    }
    __syncthreads();

    // phase 3: num = P @ v + q @ S; out = num * rden (rounded + k-interleaved)
    {
        float acc[4][4];
#pragma unroll
        for (int nt = 0; nt < 4; nt++)
#pragma unroll
            for (int i = 0; i < 4; i++) acc[nt][i] = 0.f;

#pragma unroll
        for (int kk = 0; kk < 8; kk++) {       // P @ v  (K = s)
            const int k0 = kk * 8;
            uint32_t a[4];
            a[0] = f2tf32(sm[OP + (wm + g    ) * IP + k0 + tig    ]);
            a[1] = f2tf32(sm[OP + (wm + g + 8) * IP + k0 + tig    ]);
            a[2] = f2tf32(sm[OP + (wm + g    ) * IP + k0 + tig + 4]);
            a[3] = f2tf32(sm[OP + (wm + g + 8) * IP + k0 + tig + 4]);
#pragma unroll
            for (int nt = 0; nt < 4; nt++) {
                uint32_t b0 = f2tf32(sm[OV + (wn + nt * 8 + g) * TP + k0 + tig    ]);
                uint32_t b1 = f2tf32(sm[OV + (wn + nt * 8 + g) * TP + k0 + tig + 4]);
                mma_tf32(acc[nt], a, b0, b1);
            }
        }
#pragma unroll
        for (int kk = 0; kk < 8; kk++) {       // q @ S_T  (K = e)
            const int k0 = kk * 8;
            uint32_t a[4];
            a[0] = f2tf32(sm[OQ + (wm + g    ) * IP + k0 + tig    ]);
            a[1] = f2tf32(sm[OQ + (wm + g + 8) * IP + k0 + tig    ]);
            a[2] = f2tf32(sm[OQ + (wm + g    ) * IP + k0 + tig + 4]);
            a[3] = f2tf32(sm[OQ + (wm + g + 8) * IP + k0 + tig + 4]);
#pragma unroll
            for (int nt = 0; nt < 4; nt++) {
                uint32_t b0 = f2tf32(sm[OS + (wn + nt * 8 + g) * IP + k0 + tig    ]);
                uint32_t b1 = f2tf32(sm[OS + (wn + nt * 8 + g) * IP + k0 + tig + 4]);
                mma_tf32(acc[nt], a, b0, b1);
            }
        }

        const float rd0 = sm[ODEN + wm + g];
        const float rd1 = sm[ODEN + wm + g + 8];
        // k-interleaved store positions for logical cols (2*tig, 2*tig+1)
        const int pj0 = (tig < 2) ? 4 * tig     : 4 * tig - 7;
        const int pj1 = (tig < 2) ? 4 * tig + 2 : 4 * tig - 5;
#pragma unroll
        for (int nt = 0; nt < 4; nt++) {
            const int colb = h * EE + wn + nt * 8;
            float* r0p = g_attn + (size_t)(rowbase + wm + g    ) * DD + colb;
            float* r1p = g_attn + (size_t)(rowbase + wm + g + 8) * DD + colb;
            r0p[pj0] = rtf(acc[nt][0] * rd0);
            r0p[pj1] = rtf(acc[nt][1] * rd0);
            r1p[pj0] = rtf(acc[nt][2] * rd1);
            r1p[pj1] = rtf(acc[nt][3] * rd1);
        }
    }
}

// ---------------- RMSNorm ----------------
__global__ __launch_bounds__(128)
void rmsnorm_kernel(const float* __restrict__ scale, float* __restrict__ out)
{
    const int m = blockIdx.x;
    const int tid = threadIdx.x;
    float4 v = *(const float4*)(g_proj + (size_t)m * DD + tid * 4);
    float ss = v.x * v.x + v.y * v.y + v.z * v.z + v.w * v.w;
#pragma unroll
    for (int off = 16; off; off >>= 1) ss += __shfl_xor_sync(0xffffffffu, ss, off);
    __shared__ float ws[4];
    if ((tid & 31) == 0) ws[tid >> 5] = ss;
    __syncthreads();
    float tot = ws[0] + ws[1] + ws[2] + ws[3];
    float rn = rsqrtf(tot * (1.f / DD) + 1e-8f);
    float4 sc = *(const float4*)(scale + tid * 4);
    float4 o;
    o.x = v.x * rn * sc.x; o.y = v.y * rn * sc.y;
    o.z = v.z * rn * sc.z; o.w = v.w * rn * sc.w;
    *(float4*)(out + (size_t)m * DD + tid * 4) = o;
}

// ---------------- launch ----------------
extern "C" void kernel_launch(void* const* d_in, const int* in_sizes, int n_in,
                              void* d_out, int out_size)
{
    const float* x          = (const float*)d_in[0];
    const float* qkv_w      = (const float*)d_in[1];
    const float* qkv_b      = (const float*)d_in[2];
    const float* out_w      = (const float*)d_in[3];
    const float* out_b      = (const float*)d_in[4];
    const float* decay_w    = (const float*)d_in[5];
    const float* decay_b    = (const float*)d_in[6];
    const float* norm_scale = (const float*)d_in[7];
    float* out = (float*)d_out;

    const int gsm = 4 * ASZ * (int)sizeof(float);   // 81920 B
    cudaFuncSetAttribute(gemm_tc<0>, cudaFuncAttributeMaxDynamicSharedMemorySize, gsm);
    cudaFuncSetAttribute(gemm_tc<1>, cudaFuncAttributeMaxDynamicSharedMemorySize, gsm);
    const int ism = ISMF * (int)sizeof(float);
    cudaFuncSetAttribute(intra_mma, cudaFuncAttributeMaxDynamicSharedMemorySize, ism);

    // total 8-float units: (3*DD*DD + DD*DD + MM*DD)/8 = 655360 -> 2560 blocks
    decay_kernel<<<MM, 256>>>(x, decay_w, decay_b);            // #1
    cumsum_kernel<<<BB * HH, 256>>>();                         // #2
    roundw_kernel<<<2560, 256>>>(qkv_w, out_w, x);             // #3
    gemm_tc<0><<<dim3(12, 64), 256, gsm>>>(qkv_b);             // #4  <- ncu capture slot
    chunkstate_mma<<<BB * HH * NC, 128>>>();                   // #5
    statescan_kernel<<<BB * HH * 16, 256>>>();                 // #6
    intra_mma<<<BB * HH * NC, 256, ism>>>();                   // #7
    gemm_tc<1><<<dim3(4, 64), 256, gsm>>>(out_b);              // #8
    rmsnorm_kernel<<<MM, 128>>>(norm_scale, out);              // #9
}